// round 13
// baseline (speedup 1.0000x reference)
#include <cuda_runtime.h>
#include <cuda_bf16.h>
#include <math.h>
#include <stdint.h>

// Problem constants
#define BSZ 2
#define LSEQ 1024
#define DMODEL 1024
#define DINNER 2048
#define NSTATE 16
#define DTRANK 64
#define CHUNK 256
#define NTOK (BSZ*LSEQ)          // 2048
#define XPC (DTRANK + 2*NSTATE)  // 96
#define XP_KSPLIT 8

// ---------------------------------------------------------------------------
// Low-level helpers
// ---------------------------------------------------------------------------
__device__ __forceinline__ uint32_t smem_to_u32(const void* p) {
    uint32_t a;
    asm("{ .reg .u64 t; cvta.to.shared.u64 t, %1; cvt.u32.u64 %0, t; }" : "=r"(a) : "l"(p));
    return a;
}
__device__ __forceinline__ void cp16(uint32_t dst, const void* src) {
    asm volatile("cp.async.cg.shared.global [%0], [%1], 16;" :: "r"(dst), "l"(src));
}
__device__ __forceinline__ void ldsm_x4(uint32_t* r, uint32_t addr) {
    asm volatile("ldmatrix.sync.aligned.m8n8.x4.shared.b16 {%0,%1,%2,%3}, [%4];"
                 : "=r"(r[0]), "=r"(r[1]), "=r"(r[2]), "=r"(r[3]) : "r"(addr));
}
__device__ __forceinline__ void mma16816(float* c, const uint32_t* a, const uint32_t* b) {
    asm volatile(
        "mma.sync.aligned.m16n8k16.row.col.f32.bf16.bf16.f32 "
        "{%0,%1,%2,%3}, {%4,%5,%6,%7}, {%8,%9}, {%0,%1,%2,%3};"
        : "+f"(c[0]), "+f"(c[1]), "+f"(c[2]), "+f"(c[3])
        : "r"(a[0]), "r"(a[1]), "r"(a[2]), "r"(a[3]), "r"(b[0]), "r"(b[1]));
}

// ---------------------------------------------------------------------------
// Scratch (device globals)
// ---------------------------------------------------------------------------
__device__ __align__(16) float g_xr[(size_t)NTOK * 2 * DINNER];
__device__ __align__(16) float g_xp[(size_t)NTOK * XPC];
__device__ __align__(16) float g_xp_part[(size_t)XP_KSPLIT * NTOK * XPC];
__device__ __align__(16) float g_delta[(size_t)NTOK * DINNER];

__device__ __align__(16) __nv_bfloat16 g_x_hi[(size_t)NTOK * DMODEL];
__device__ __align__(16) __nv_bfloat16 g_x_lo[(size_t)NTOK * DMODEL];
__device__ __align__(16) __nv_bfloat16 g_Win_hi[(size_t)2 * DINNER * DMODEL];
__device__ __align__(16) __nv_bfloat16 g_Win_lo[(size_t)2 * DINNER * DMODEL];
__device__ __align__(16) __nv_bfloat16 g_Wx_hi[(size_t)XPC * DINNER];
__device__ __align__(16) __nv_bfloat16 g_Wx_lo[(size_t)XPC * DINNER];
__device__ __align__(16) __nv_bfloat16 g_Wdt_hi[(size_t)DINNER * DTRANK];
__device__ __align__(16) __nv_bfloat16 g_Wdt_lo[(size_t)DINNER * DTRANK];
__device__ __align__(16) __nv_bfloat16 g_Wout_hi[(size_t)DMODEL * DINNER];
__device__ __align__(16) __nv_bfloat16 g_Wout_lo[(size_t)DMODEL * DINNER];
__device__ __align__(16) __nv_bfloat16 g_u_hi[(size_t)NTOK * DINNER];
__device__ __align__(16) __nv_bfloat16 g_u_lo[(size_t)NTOK * DINNER];
__device__ __align__(16) __nv_bfloat16 g_xp_hi[(size_t)NTOK * XPC];
__device__ __align__(16) __nv_bfloat16 g_xp_lo[(size_t)NTOK * XPC];
__device__ __align__(16) __nv_bfloat16 g_g_hi[(size_t)NTOK * DINNER];
__device__ __align__(16) __nv_bfloat16 g_g_lo[(size_t)NTOK * DINNER];

__device__ __forceinline__ float silu_f(float x) { return x / (1.0f + __expf(-x)); }
__device__ __forceinline__ void split_bf16(float v, __nv_bfloat16& h, __nv_bfloat16& l) {
    h = __float2bfloat16(v);
    l = __float2bfloat16(v - __bfloat162float(h));
}
__device__ __forceinline__ uint32_t pack2(__nv_bfloat16 a, __nv_bfloat16 b) {
    return ((uint32_t)__bfloat16_as_ushort(b) << 16) | (uint32_t)__bfloat16_as_ushort(a);
}

// ---------------------------------------------------------------------------
// One merged conversion kernel for all fp32 -> (hi,lo) bf16 splits
// ---------------------------------------------------------------------------
#define CV0 (NTOK * DMODEL / 4)
#define CV1 (CV0 + 2 * DINNER * DMODEL / 4)
#define CV2 (CV1 + XPC * DINNER / 4)
#define CV3 (CV2 + DINNER * DTRANK / 4)
#define CV4 (CV3 + DMODEL * DINNER / 4)

__device__ __forceinline__ void cvt4(const float* __restrict__ in,
                                     __nv_bfloat16* __restrict__ hi,
                                     __nv_bfloat16* __restrict__ lo, int i) {
    float4 v = ((const float4*)in)[i];
    __nv_bfloat16 h0, h1, h2, h3, l0, l1, l2, l3;
    split_bf16(v.x, h0, l0); split_bf16(v.y, h1, l1);
    split_bf16(v.z, h2, l2); split_bf16(v.w, h3, l3);
    ((uint2*)hi)[i] = make_uint2(pack2(h0, h1), pack2(h2, h3));
    ((uint2*)lo)[i] = make_uint2(pack2(l0, l1), pack2(l2, l3));
}

__global__ void cvt_all_kernel(const float* __restrict__ x,
                               const float* __restrict__ Wi,
                               const float* __restrict__ Wx,
                               const float* __restrict__ Wd,
                               const float* __restrict__ Wo) {
    int i = blockIdx.x * blockDim.x + threadIdx.x;
    if (i < CV0)            cvt4(x,  g_x_hi,   g_x_lo,   i);
    else if (i < CV1)       cvt4(Wi, g_Win_hi, g_Win_lo, i - CV0);
    else if (i < CV2)       cvt4(Wx, g_Wx_hi,  g_Wx_lo,  i - CV1);
    else if (i < CV3)       cvt4(Wd, g_Wdt_hi, g_Wdt_lo, i - CV2);
    else if (i < CV4)       cvt4(Wo, g_Wout_hi, g_Wout_lo, i - CV3);
}

// ---------------------------------------------------------------------------
// mma.sync split-bf16 GEMM (R6/R3 config): CTA 128x128, BK=32, 512 threads,
// 2-stage cp.async, XOR swizzle on 16B chunks within 64B rows.
// 3-term accumulation: AhiWhi + AhiWlo + AloWhi (fp32 accum in registers).
// ---------------------------------------------------------------------------
#define STG_BYTES 32768      // per stage: 4 tiles x 8192
#define GEMM_SMEM (2 * STG_BYTES)

__device__ __forceinline__ uint32_t swz(int row, int c) {
    return (uint32_t)(row * 64 + ((c ^ ((row >> 1) & 3)) << 4));
}

template<int ACT>
__global__ __launch_bounds__(512, 1)
void gemm_mma_kernel(const __nv_bfloat16* __restrict__ Ahi, const __nv_bfloat16* __restrict__ Alo, int lda,
                     const __nv_bfloat16* __restrict__ Whi, const __nv_bfloat16* __restrict__ Wlo, int ldw,
                     const float* __restrict__ bias, float* __restrict__ C, int ldc,
                     int Nvalid, int K, long czstride) {
    extern __shared__ __align__(1024) char smem[];
    const uint32_t sbase = smem_to_u32(smem);
    const int tid = threadIdx.x;
    const int lane = tid & 31, wid = tid >> 5;
    const int wm = wid & 3, wn = wid >> 2;
    const int bm = blockIdx.y * 128, bn = blockIdx.x * 128;
    const int kbase = blockIdx.z * K;
    float* Cz = C + (size_t)blockIdx.z * czstride;

    // zero-fill W tile rows >= Nvalid (xp case), both stages, both W tiles
    if (bn + 128 > Nvalid) {
        for (int j = tid; j < 2 * 2 * 128 * 4; j += 512) {
            int c = j & 3, r = (j >> 2) & 127, t = (j >> 9) & 1, s = j >> 10;
            if (bn + r >= Nvalid)
                *(uint4*)(smem + s * STG_BYTES + (2 + t) * 8192 + swz(r, c)) = make_uint4(0, 0, 0, 0);
        }
        __syncthreads();
    }

    const int nIter = K / 32;
    const int r = tid >> 2, c = tid & 3;
    const uint32_t dswz = swz(r, c);
    const bool wok = (bn + r < Nvalid);

    auto issue = [&](int stage, int k0) {
        uint32_t dst = sbase + stage * STG_BYTES + dswz;
        const char* a0 = (const char*)Ahi + ((size_t)(bm + r) * lda + k0) * 2 + c * 16;
        const char* a1 = (const char*)Alo + ((size_t)(bm + r) * lda + k0) * 2 + c * 16;
        cp16(dst, a0);
        cp16(dst + 8192, a1);
        if (wok) {
            const char* w0 = (const char*)Whi + ((size_t)(bn + r) * ldw + k0) * 2 + c * 16;
            const char* w1 = (const char*)Wlo + ((size_t)(bn + r) * ldw + k0) * 2 + c * 16;
            cp16(dst + 16384, w0);
            cp16(dst + 24576, w1);
        }
    };

    issue(0, kbase);
    asm volatile("cp.async.commit_group;" ::: "memory");
    if (nIter > 1) {
        issue(1, kbase + 32);
        asm volatile("cp.async.commit_group;" ::: "memory");
    }

    float acc[2][4][4];
#pragma unroll
    for (int mi = 0; mi < 2; mi++)
#pragma unroll
        for (int nt = 0; nt < 4; nt++)
#pragma unroll
            for (int q = 0; q < 4; q++) acc[mi][nt][q] = 0.0f;

    for (int it = 0; it < nIter; it++) {
        if (it + 1 < nIter) asm volatile("cp.async.wait_group 1;" ::: "memory");
        else                asm volatile("cp.async.wait_group 0;" ::: "memory");
        __syncthreads();
        const uint32_t sA_hi = sbase + (it & 1) * STG_BYTES;
        const uint32_t sA_lo = sA_hi + 8192;
        const uint32_t sW_hi = sA_hi + 16384;
        const uint32_t sW_lo = sA_hi + 24576;

#pragma unroll
        for (int ks = 0; ks < 2; ks++) {
            uint32_t ah[2][4], al[2][4], bh[4][2], bl[4][2];
#pragma unroll
            for (int mi = 0; mi < 2; mi++) {
                int rr = wm * 32 + mi * 16 + (lane & 15);
                int kc = 2 * ks + (lane >> 4);
                uint32_t addr = swz(rr, kc);
                ldsm_x4(ah[mi], sA_hi + addr);
                ldsm_x4(al[mi], sA_lo + addr);
            }
#pragma unroll
            for (int njp = 0; njp < 2; njp++) {
                int seg = lane >> 3;
                int rr = wn * 32 + njp * 16 + ((seg >> 1) << 3) + (lane & 7);
                int kc = 2 * ks + (seg & 1);
                uint32_t addr = swz(rr, kc);
                uint32_t t0[4], t1[4];
                ldsm_x4(t0, sW_hi + addr);
                ldsm_x4(t1, sW_lo + addr);
                bh[njp * 2][0] = t0[0]; bh[njp * 2][1] = t0[1];
                bh[njp * 2 + 1][0] = t0[2]; bh[njp * 2 + 1][1] = t0[3];
                bl[njp * 2][0] = t1[0]; bl[njp * 2][1] = t1[1];
                bl[njp * 2 + 1][0] = t1[2]; bl[njp * 2 + 1][1] = t1[3];
            }
#pragma unroll
            for (int mi = 0; mi < 2; mi++)
#pragma unroll
                for (int nt = 0; nt < 4; nt++) {
                    mma16816(acc[mi][nt], ah[mi], bh[nt]);
                    mma16816(acc[mi][nt], ah[mi], bl[nt]);
                    mma16816(acc[mi][nt], al[mi], bh[nt]);
                }
        }
        __syncthreads();
        if (it + 2 < nIter) {
            issue(it & 1, kbase + (it + 2) * 32);
            asm volatile("cp.async.commit_group;" ::: "memory");
        }
    }

    // epilogue: direct register stores
    const int g = lane >> 2, tig = lane & 3;
#pragma unroll
    for (int mi = 0; mi < 2; mi++) {
        int m0 = bm + wm * 32 + mi * 16 + g;
#pragma unroll
        for (int nt = 0; nt < 4; nt++) {
            int n = bn + wn * 32 + nt * 8 + tig * 2;
            if (n < Nvalid) {
                float b0 = bias ? bias[n] : 0.0f;
                float b1 = bias ? bias[n + 1] : 0.0f;
                float v0 = acc[mi][nt][0] + b0, v1 = acc[mi][nt][1] + b1;
                float v2 = acc[mi][nt][2] + b0, v3 = acc[mi][nt][3] + b1;
                if (ACT == 1) {
                    v0 = (v0 > 20.0f) ? v0 : log1pf(__expf(v0));
                    v1 = (v1 > 20.0f) ? v1 : log1pf(__expf(v1));
                    v2 = (v2 > 20.0f) ? v2 : log1pf(__expf(v2));
                    v3 = (v3 > 20.0f) ? v3 : log1pf(__expf(v3));
                }
                *(float2*)&Cz[(size_t)m0 * ldc + n] = make_float2(v0, v1);
                *(float2*)&Cz[(size_t)(m0 + 8) * ldc + n] = make_float2(v2, v3);
            }
        }
    }
}

// ---------------------------------------------------------------------------
// Depthwise causal conv1d (k=3) + bias + SiLU -> u hi/lo bf16 only, x4
// ---------------------------------------------------------------------------
__global__ void conv_silu_kernel(const float* __restrict__ cw,
                                 const float* __restrict__ cb) {
    int i = blockIdx.x * blockDim.x + threadIdx.x;   // over NTOK*DINNER/4
    if (i >= NTOK * DINNER / 4) return;
    int d4 = (i & (DINNER / 4 - 1)) * 4;
    int bl = i / (DINNER / 4);
    int l = bl & (LSEQ - 1);

    const float* base = g_xr + (size_t)bl * (2 * DINNER) + d4;
    float4 cur = *(const float4*)base;
    float4 p1 = make_float4(0, 0, 0, 0), p2 = p1;
    if (l >= 1) p1 = *(const float4*)(base - 2 * DINNER);
    if (l >= 2) p2 = *(const float4*)(base - 4 * DINNER);

    float u4[4];
#pragma unroll
    for (int q = 0; q < 4; q++) {
        int d = d4 + q;
        float w0 = __ldg(cw + d * 3 + 0);
        float w1 = __ldg(cw + d * 3 + 1);
        float w2 = __ldg(cw + d * 3 + 2);
        float c = (&cur.x)[q], a = (&p1.x)[q], b = (&p2.x)[q];
        float acc = __ldg(cb + d) + w2 * c;
        acc = fmaf(w1, a, acc);
        acc = fmaf(w0, b, acc);
        u4[q] = silu_f(acc);
    }
    __nv_bfloat16 h0, h1, h2, h3, l0, l1, l2, l3;
    split_bf16(u4[0], h0, l0); split_bf16(u4[1], h1, l1);
    split_bf16(u4[2], h2, l2); split_bf16(u4[3], h3, l3);
    ((uint2*)g_u_hi)[i] = make_uint2(pack2(h0, h1), pack2(h2, h3));
    ((uint2*)g_u_lo)[i] = make_uint2(pack2(l0, l1), pack2(l2, l3));
}

// ---------------------------------------------------------------------------
// Reduce x_proj K-split partials -> g_xp fp32 + hi/lo
// ---------------------------------------------------------------------------
__global__ void xp_reduce_kernel() {
    int i = blockIdx.x * blockDim.x + threadIdx.x;
    if (i >= NTOK * XPC) return;
    float s = 0.0f;
#pragma unroll
    for (int z = 0; z < XP_KSPLIT; z++)
        s += g_xp_part[(size_t)z * NTOK * XPC + i];
    g_xp[i] = s;
    __nv_bfloat16 h, lo;
    split_bf16(s, h, lo);
    g_xp_hi[i] = h;
    g_xp_lo[i] = lo;
}

// ---------------------------------------------------------------------------
// Chunked selective scan + fused gate: 8 lanes per d-channel, 2 states/lane.
// Warp covers 4 d. Block: 256 threads = 8 warps = 32 d.
// Grid: (DINNER/32, L/CHUNK, B) = (64, 4, 2).
// u reconstructed from bf16 hi/lo; res prefetched one t ahead; output is
// g = y * silu(res) as bf16 hi/lo (A operand of out_proj).
// ---------------------------------------------------------------------------
__global__ __launch_bounds__(256)
void scan_kernel(const float* __restrict__ A_log) {
    __shared__ float sBC[CHUNK][2 * NSTATE];
    const int b = blockIdx.z;
    const int c = blockIdx.y;
    const int tid = threadIdx.x;
    const int lane = tid & 31, wid = tid >> 5;
    const int g = lane >> 3;            // d within warp (0..3)
    const int j = lane & 7;             // state pair index (handles j and j+8)
    const int d = blockIdx.x * 32 + wid * 4 + g;
    const size_t row0 = (size_t)(b * LSEQ + c * CHUNK);

    for (int i = tid; i < CHUNK * 32; i += 256) {
        int t = i >> 5, k = i & 31;
        sBC[t][k] = g_xp[(row0 + t) * XPC + DTRANK + k];
    }

    const float A0 = -__expf(__ldg(A_log + d * NSTATE + j));
    const float A1 = -__expf(__ldg(A_log + d * NSTATE + j + 8));
    float s0 = 0.0f, s1 = 0.0f;
    __syncthreads();

    const float* dp = g_delta + row0 * DINNER + d;
    const __nv_bfloat16* uhp = g_u_hi + row0 * DINNER + d;
    const __nv_bfloat16* ulp = g_u_lo + row0 * DINNER + d;
    const float* rp = g_xr + row0 * (2 * DINNER) + DINNER + d;
    __nv_bfloat16* ghp = g_g_hi + row0 * DINNER + d;
    __nv_bfloat16* glp = g_g_lo + row0 * DINNER + d;

    float dl = dp[0];
    float ut = __bfloat162float(uhp[0]) + __bfloat162float(ulp[0]);
    float rs = rp[0];
#pragma unroll 2
    for (int t = 0; t < CHUNK; t++) {
        float dln = 0.f, utn = 0.f, rsn = 0.f;
        if (t + 1 < CHUNK) {
            dln = __ldg(dp + (size_t)(t + 1) * DINNER);
            utn = __bfloat162float(__ldg(uhp + (size_t)(t + 1) * DINNER)) +
                  __bfloat162float(__ldg(ulp + (size_t)(t + 1) * DINNER));
            rsn = __ldg(rp + (size_t)(t + 1) * (2 * DINNER));
        }
        float du = dl * ut;
        float a0 = __expf(dl * A0);
        float a1 = __expf(dl * A1);
        s0 = fmaf(a0, s0, du * sBC[t][j]);
        s1 = fmaf(a1, s1, du * sBC[t][j + 8]);
        float p = fmaf(s1, sBC[t][NSTATE + j + 8], s0 * sBC[t][NSTATE + j]);
        p += __shfl_xor_sync(0xffffffffu, p, 1, 8);
        p += __shfl_xor_sync(0xffffffffu, p, 2, 8);
        p += __shfl_xor_sync(0xffffffffu, p, 4, 8);
        if (j == 0) {
            float gv = p * silu_f(rs);
            __nv_bfloat16 h, lo;
            split_bf16(gv, h, lo);
            ghp[(size_t)t * DINNER] = h;
            glp[(size_t)t * DINNER] = lo;
        }
        dl = dln; ut = utn; rs = rsn;
    }
}

// ---------------------------------------------------------------------------
// Host launch
// ---------------------------------------------------------------------------
extern "C" void kernel_launch(void* const* d_in, const int* in_sizes, int n_in,
                              void* d_out, int out_size) {
    const float* x      = (const float*)d_in[0];
    const float* W_in   = (const float*)d_in[1];
    const float* b_in   = (const float*)d_in[2];
    const float* conv_w = (const float*)d_in[3];
    const float* conv_b = (const float*)d_in[4];
    const float* W_x    = (const float*)d_in[5];
    const float* W_dt   = (const float*)d_in[6];
    const float* b_dt   = (const float*)d_in[7];
    const float* A_log  = (const float*)d_in[8];
    const float* W_out  = (const float*)d_in[9];
    const float* b_out  = (const float*)d_in[10];
    float* out = (float*)d_out;

    cudaFuncSetAttribute(gemm_mma_kernel<0>, cudaFuncAttributeMaxDynamicSharedMemorySize, GEMM_SMEM);
    cudaFuncSetAttribute(gemm_mma_kernel<1>, cudaFuncAttributeMaxDynamicSharedMemorySize, GEMM_SMEM);

    float *p_xr, *p_xp_part, *p_delta;
    cudaGetSymbolAddress((void**)&p_xr, g_xr);
    cudaGetSymbolAddress((void**)&p_xp_part, g_xp_part);
    cudaGetSymbolAddress((void**)&p_delta, g_delta);

    __nv_bfloat16 *xh, *xl, *wih, *wil, *wxh, *wxl, *wdh, *wdl, *woh, *wol;
    __nv_bfloat16 *uh, *ul, *xph, *xpl, *gh, *gl;
    cudaGetSymbolAddress((void**)&xh, g_x_hi);    cudaGetSymbolAddress((void**)&xl, g_x_lo);
    cudaGetSymbolAddress((void**)&wih, g_Win_hi); cudaGetSymbolAddress((void**)&wil, g_Win_lo);
    cudaGetSymbolAddress((void**)&wxh, g_Wx_hi);  cudaGetSymbolAddress((void**)&wxl, g_Wx_lo);
    cudaGetSymbolAddress((void**)&wdh, g_Wdt_hi); cudaGetSymbolAddress((void**)&wdl, g_Wdt_lo);
    cudaGetSymbolAddress((void**)&woh, g_Wout_hi); cudaGetSymbolAddress((void**)&wol, g_Wout_lo);
    cudaGetSymbolAddress((void**)&uh, g_u_hi);    cudaGetSymbolAddress((void**)&ul, g_u_lo);
    cudaGetSymbolAddress((void**)&xph, g_xp_hi);  cudaGetSymbolAddress((void**)&xpl, g_xp_lo);
    cudaGetSymbolAddress((void**)&gh, g_g_hi);    cudaGetSymbolAddress((void**)&gl, g_g_lo);

    // 0) all split-bf16 conversions in one launch
    cvt_all_kernel<<<(CV4 + 255) / 256, 256>>>(x, W_in, W_x, W_dt, W_out);

    // 1) in_proj: xr = x @ W_in^T + b_in   (2048 x 4096, K=1024)
    gemm_mma_kernel<0><<<dim3(32, 16, 1), 512, GEMM_SMEM>>>(
        xh, xl, DMODEL, wih, wil, DMODEL, b_in, p_xr, 2 * DINNER, 2 * DINNER, 1024, 0);

    // 2) depthwise conv + SiLU -> u (bf16 hi/lo only)
    conv_silu_kernel<<<(NTOK * DINNER / 4 + 255) / 256, 256>>>(conv_w, conv_b);

    // 3) x_proj: xp = u @ W_x^T  (2048 x 96, K=2048), K-split 8 + reduce
    gemm_mma_kernel<0><<<dim3(1, 16, XP_KSPLIT), 512, GEMM_SMEM>>>(
        uh, ul, DINNER, wxh, wxl, DINNER, nullptr, p_xp_part, XPC, XPC,
        DINNER / XP_KSPLIT, (long)NTOK * XPC);
    xp_reduce_kernel<<<(NTOK * XPC + 255) / 256, 256>>>();

    // 4) delta = softplus(dlt @ W_dt^T + b_dt)  (2048 x 2048, K=64)
    gemm_mma_kernel<1><<<dim3(16, 16, 1), 512, GEMM_SMEM>>>(
        xph, xpl, XPC, wdh, wdl, DTRANK, b_dt, p_delta, DINNER, DINNER, 64, 0);

    // 5) chunked selective scan + fused gate -> g (bf16 hi/lo)
    scan_kernel<<<dim3(DINNER / 32, LSEQ / CHUNK, BSZ), 256>>>(A_log);

    // 6) out = g @ W_out^T + b_out  (2048 x 1024, K=2048)
    gemm_mma_kernel<0><<<dim3(8, 16, 1), 512, GEMM_SMEM>>>(
        gh, gl, DINNER, woh, wol, DINNER, b_out, out, DMODEL, DMODEL, 2048, 0);
}

// round 15
// speedup vs baseline: 1.1644x; 1.1644x over previous
#include <cuda_runtime.h>
#include <cuda_bf16.h>
#include <math.h>
#include <stdint.h>

// Problem constants
#define BSZ 2
#define LSEQ 1024
#define DMODEL 1024
#define DINNER 2048
#define NSTATE 16
#define DTRANK 64
#define CHUNK 256
#define NTOK (BSZ*LSEQ)          // 2048
#define XPC (DTRANK + 2*NSTATE)  // 96
#define XP_KSPLIT 8

// ---------------------------------------------------------------------------
// Low-level helpers
// ---------------------------------------------------------------------------
__device__ __forceinline__ uint32_t smem_to_u32(const void* p) {
    uint32_t a;
    asm("{ .reg .u64 t; cvta.to.shared.u64 t, %1; cvt.u32.u64 %0, t; }" : "=r"(a) : "l"(p));
    return a;
}
__device__ __forceinline__ void cp16(uint32_t dst, const void* src) {
    asm volatile("cp.async.cg.shared.global [%0], [%1], 16;" :: "r"(dst), "l"(src));
}
__device__ __forceinline__ void ldsm_x4(uint32_t* r, uint32_t addr) {
    asm volatile("ldmatrix.sync.aligned.m8n8.x4.shared.b16 {%0,%1,%2,%3}, [%4];"
                 : "=r"(r[0]), "=r"(r[1]), "=r"(r[2]), "=r"(r[3]) : "r"(addr));
}
__device__ __forceinline__ void mma16816(float* c, const uint32_t* a, const uint32_t* b) {
    asm volatile(
        "mma.sync.aligned.m16n8k16.row.col.f32.bf16.bf16.f32 "
        "{%0,%1,%2,%3}, {%4,%5,%6,%7}, {%8,%9}, {%0,%1,%2,%3};"
        : "+f"(c[0]), "+f"(c[1]), "+f"(c[2]), "+f"(c[3])
        : "r"(a[0]), "r"(a[1]), "r"(a[2]), "r"(a[3]), "r"(b[0]), "r"(b[1]));
}

// ---------------------------------------------------------------------------
// Scratch (device globals)
// ---------------------------------------------------------------------------
__device__ __align__(16) float g_xr[(size_t)NTOK * 2 * DINNER];
__device__ __align__(16) float g_xp[(size_t)NTOK * XPC];
__device__ __align__(16) float g_xp_part[(size_t)XP_KSPLIT * NTOK * XPC];
__device__ __align__(16) float g_delta[(size_t)NTOK * DINNER];
__device__ __align__(16) float g_y[(size_t)NTOK * DINNER];

__device__ __align__(16) __nv_bfloat16 g_x_hi[(size_t)NTOK * DMODEL];
__device__ __align__(16) __nv_bfloat16 g_x_lo[(size_t)NTOK * DMODEL];
__device__ __align__(16) __nv_bfloat16 g_Win_hi[(size_t)2 * DINNER * DMODEL];
__device__ __align__(16) __nv_bfloat16 g_Win_lo[(size_t)2 * DINNER * DMODEL];
__device__ __align__(16) __nv_bfloat16 g_Wx_hi[(size_t)XPC * DINNER];
__device__ __align__(16) __nv_bfloat16 g_Wx_lo[(size_t)XPC * DINNER];
__device__ __align__(16) __nv_bfloat16 g_Wdt_hi[(size_t)DINNER * DTRANK];
__device__ __align__(16) __nv_bfloat16 g_Wdt_lo[(size_t)DINNER * DTRANK];
__device__ __align__(16) __nv_bfloat16 g_Wout_hi[(size_t)DMODEL * DINNER];
__device__ __align__(16) __nv_bfloat16 g_Wout_lo[(size_t)DMODEL * DINNER];
__device__ __align__(16) __nv_bfloat16 g_u_hi[(size_t)NTOK * DINNER];
__device__ __align__(16) __nv_bfloat16 g_u_lo[(size_t)NTOK * DINNER];
__device__ __align__(16) __nv_bfloat16 g_xp_hi[(size_t)NTOK * XPC];
__device__ __align__(16) __nv_bfloat16 g_xp_lo[(size_t)NTOK * XPC];
__device__ __align__(16) __nv_bfloat16 g_g_hi[(size_t)NTOK * DINNER];
__device__ __align__(16) __nv_bfloat16 g_g_lo[(size_t)NTOK * DINNER];

__device__ __forceinline__ float silu_f(float x) { return x / (1.0f + __expf(-x)); }
__device__ __forceinline__ void split_bf16(float v, __nv_bfloat16& h, __nv_bfloat16& l) {
    h = __float2bfloat16(v);
    l = __float2bfloat16(v - __bfloat162float(h));
}
__device__ __forceinline__ uint32_t pack2(__nv_bfloat16 a, __nv_bfloat16 b) {
    return ((uint32_t)__bfloat16_as_ushort(b) << 16) | (uint32_t)__bfloat16_as_ushort(a);
}

// ---------------------------------------------------------------------------
// One merged conversion kernel for all fp32 -> (hi,lo) bf16 splits
// ---------------------------------------------------------------------------
#define CV0 (NTOK * DMODEL / 4)
#define CV1 (CV0 + 2 * DINNER * DMODEL / 4)
#define CV2 (CV1 + XPC * DINNER / 4)
#define CV3 (CV2 + DINNER * DTRANK / 4)
#define CV4 (CV3 + DMODEL * DINNER / 4)

__device__ __forceinline__ void cvt4(const float* __restrict__ in,
                                     __nv_bfloat16* __restrict__ hi,
                                     __nv_bfloat16* __restrict__ lo, int i) {
    float4 v = ((const float4*)in)[i];
    __nv_bfloat16 h0, h1, h2, h3, l0, l1, l2, l3;
    split_bf16(v.x, h0, l0); split_bf16(v.y, h1, l1);
    split_bf16(v.z, h2, l2); split_bf16(v.w, h3, l3);
    ((uint2*)hi)[i] = make_uint2(pack2(h0, h1), pack2(h2, h3));
    ((uint2*)lo)[i] = make_uint2(pack2(l0, l1), pack2(l2, l3));
}

__global__ void cvt_all_kernel(const float* __restrict__ x,
                               const float* __restrict__ Wi,
                               const float* __restrict__ Wx,
                               const float* __restrict__ Wd,
                               const float* __restrict__ Wo) {
    int i = blockIdx.x * blockDim.x + threadIdx.x;
    if (i < CV0)            cvt4(x,  g_x_hi,   g_x_lo,   i);
    else if (i < CV1)       cvt4(Wi, g_Win_hi, g_Win_lo, i - CV0);
    else if (i < CV2)       cvt4(Wx, g_Wx_hi,  g_Wx_lo,  i - CV1);
    else if (i < CV3)       cvt4(Wd, g_Wdt_hi, g_Wdt_lo, i - CV2);
    else if (i < CV4)       cvt4(Wo, g_Wout_hi, g_Wout_lo, i - CV3);
}

// ---------------------------------------------------------------------------
// mma.sync split-bf16 GEMM (R6/R3 config): CTA 128x128, BK=32, 512 threads,
// 2-stage cp.async, XOR swizzle on 16B chunks within 64B rows.
// 3-term accumulation: AhiWhi + AhiWlo + AloWhi (fp32 accum in registers).
// ---------------------------------------------------------------------------
#define STG_BYTES 32768      // per stage: 4 tiles x 8192
#define GEMM_SMEM (2 * STG_BYTES)

__device__ __forceinline__ uint32_t swz(int row, int c) {
    return (uint32_t)(row * 64 + ((c ^ ((row >> 1) & 3)) << 4));
}

template<int ACT>
__global__ __launch_bounds__(512, 1)
void gemm_mma_kernel(const __nv_bfloat16* __restrict__ Ahi, const __nv_bfloat16* __restrict__ Alo, int lda,
                     const __nv_bfloat16* __restrict__ Whi, const __nv_bfloat16* __restrict__ Wlo, int ldw,
                     const float* __restrict__ bias, float* __restrict__ C, int ldc,
                     int Nvalid, int K, long czstride) {
    extern __shared__ __align__(1024) char smem[];
    const uint32_t sbase = smem_to_u32(smem);
    const int tid = threadIdx.x;
    const int lane = tid & 31, wid = tid >> 5;
    const int wm = wid & 3, wn = wid >> 2;
    const int bm = blockIdx.y * 128, bn = blockIdx.x * 128;
    const int kbase = blockIdx.z * K;
    float* Cz = C + (size_t)blockIdx.z * czstride;

    // zero-fill W tile rows >= Nvalid (xp case), both stages, both W tiles
    if (bn + 128 > Nvalid) {
        for (int j = tid; j < 2 * 2 * 128 * 4; j += 512) {
            int c = j & 3, r = (j >> 2) & 127, t = (j >> 9) & 1, s = j >> 10;
            if (bn + r >= Nvalid)
                *(uint4*)(smem + s * STG_BYTES + (2 + t) * 8192 + swz(r, c)) = make_uint4(0, 0, 0, 0);
        }
        __syncthreads();
    }

    const int nIter = K / 32;
    const int r = tid >> 2, c = tid & 3;
    const uint32_t dswz = swz(r, c);
    const bool wok = (bn + r < Nvalid);

    auto issue = [&](int stage, int k0) {
        uint32_t dst = sbase + stage * STG_BYTES + dswz;
        const char* a0 = (const char*)Ahi + ((size_t)(bm + r) * lda + k0) * 2 + c * 16;
        const char* a1 = (const char*)Alo + ((size_t)(bm + r) * lda + k0) * 2 + c * 16;
        cp16(dst, a0);
        cp16(dst + 8192, a1);
        if (wok) {
            const char* w0 = (const char*)Whi + ((size_t)(bn + r) * ldw + k0) * 2 + c * 16;
            const char* w1 = (const char*)Wlo + ((size_t)(bn + r) * ldw + k0) * 2 + c * 16;
            cp16(dst + 16384, w0);
            cp16(dst + 24576, w1);
        }
    };

    issue(0, kbase);
    asm volatile("cp.async.commit_group;" ::: "memory");
    if (nIter > 1) {
        issue(1, kbase + 32);
        asm volatile("cp.async.commit_group;" ::: "memory");
    }

    float acc[2][4][4];
#pragma unroll
    for (int mi = 0; mi < 2; mi++)
#pragma unroll
        for (int nt = 0; nt < 4; nt++)
#pragma unroll
            for (int q = 0; q < 4; q++) acc[mi][nt][q] = 0.0f;

    for (int it = 0; it < nIter; it++) {
        if (it + 1 < nIter) asm volatile("cp.async.wait_group 1;" ::: "memory");
        else                asm volatile("cp.async.wait_group 0;" ::: "memory");
        __syncthreads();
        const uint32_t sA_hi = sbase + (it & 1) * STG_BYTES;
        const uint32_t sA_lo = sA_hi + 8192;
        const uint32_t sW_hi = sA_hi + 16384;
        const uint32_t sW_lo = sA_hi + 24576;

#pragma unroll
        for (int ks = 0; ks < 2; ks++) {
            uint32_t ah[2][4], al[2][4], bh[4][2], bl[4][2];
#pragma unroll
            for (int mi = 0; mi < 2; mi++) {
                int rr = wm * 32 + mi * 16 + (lane & 15);
                int kc = 2 * ks + (lane >> 4);
                uint32_t addr = swz(rr, kc);
                ldsm_x4(ah[mi], sA_hi + addr);
                ldsm_x4(al[mi], sA_lo + addr);
            }
#pragma unroll
            for (int njp = 0; njp < 2; njp++) {
                int seg = lane >> 3;
                int rr = wn * 32 + njp * 16 + ((seg >> 1) << 3) + (lane & 7);
                int kc = 2 * ks + (seg & 1);
                uint32_t addr = swz(rr, kc);
                uint32_t t0[4], t1[4];
                ldsm_x4(t0, sW_hi + addr);
                ldsm_x4(t1, sW_lo + addr);
                bh[njp * 2][0] = t0[0]; bh[njp * 2][1] = t0[1];
                bh[njp * 2 + 1][0] = t0[2]; bh[njp * 2 + 1][1] = t0[3];
                bl[njp * 2][0] = t1[0]; bl[njp * 2][1] = t1[1];
                bl[njp * 2 + 1][0] = t1[2]; bl[njp * 2 + 1][1] = t1[3];
            }
#pragma unroll
            for (int mi = 0; mi < 2; mi++)
#pragma unroll
                for (int nt = 0; nt < 4; nt++) {
                    mma16816(acc[mi][nt], ah[mi], bh[nt]);
                    mma16816(acc[mi][nt], ah[mi], bl[nt]);
                    mma16816(acc[mi][nt], al[mi], bh[nt]);
                }
        }
        __syncthreads();
        if (it + 2 < nIter) {
            issue(it & 1, kbase + (it + 2) * 32);
            asm volatile("cp.async.commit_group;" ::: "memory");
        }
    }

    // epilogue: direct register stores
    const int g = lane >> 2, tig = lane & 3;
#pragma unroll
    for (int mi = 0; mi < 2; mi++) {
        int m0 = bm + wm * 32 + mi * 16 + g;
#pragma unroll
        for (int nt = 0; nt < 4; nt++) {
            int n = bn + wn * 32 + nt * 8 + tig * 2;
            if (n < Nvalid) {
                float b0 = bias ? bias[n] : 0.0f;
                float b1 = bias ? bias[n + 1] : 0.0f;
                float v0 = acc[mi][nt][0] + b0, v1 = acc[mi][nt][1] + b1;
                float v2 = acc[mi][nt][2] + b0, v3 = acc[mi][nt][3] + b1;
                if (ACT == 1) {
                    v0 = (v0 > 20.0f) ? v0 : log1pf(__expf(v0));
                    v1 = (v1 > 20.0f) ? v1 : log1pf(__expf(v1));
                    v2 = (v2 > 20.0f) ? v2 : log1pf(__expf(v2));
                    v3 = (v3 > 20.0f) ? v3 : log1pf(__expf(v3));
                }
                *(float2*)&Cz[(size_t)m0 * ldc + n] = make_float2(v0, v1);
                *(float2*)&Cz[(size_t)(m0 + 8) * ldc + n] = make_float2(v2, v3);
            }
        }
    }
}

// ---------------------------------------------------------------------------
// Depthwise causal conv1d (k=3) + bias + SiLU -> u hi/lo bf16 only, x4
// ---------------------------------------------------------------------------
__global__ void conv_silu_kernel(const float* __restrict__ cw,
                                 const float* __restrict__ cb) {
    int i = blockIdx.x * blockDim.x + threadIdx.x;   // over NTOK*DINNER/4
    if (i >= NTOK * DINNER / 4) return;
    int d4 = (i & (DINNER / 4 - 1)) * 4;
    int bl = i / (DINNER / 4);
    int l = bl & (LSEQ - 1);

    const float* base = g_xr + (size_t)bl * (2 * DINNER) + d4;
    float4 cur = *(const float4*)base;
    float4 p1 = make_float4(0, 0, 0, 0), p2 = p1;
    if (l >= 1) p1 = *(const float4*)(base - 2 * DINNER);
    if (l >= 2) p2 = *(const float4*)(base - 4 * DINNER);

    float u4[4];
#pragma unroll
    for (int q = 0; q < 4; q++) {
        int d = d4 + q;
        float w0 = __ldg(cw + d * 3 + 0);
        float w1 = __ldg(cw + d * 3 + 1);
        float w2 = __ldg(cw + d * 3 + 2);
        float c = (&cur.x)[q], a = (&p1.x)[q], b = (&p2.x)[q];
        float acc = __ldg(cb + d) + w2 * c;
        acc = fmaf(w1, a, acc);
        acc = fmaf(w0, b, acc);
        u4[q] = silu_f(acc);
    }
    __nv_bfloat16 h0, h1, h2, h3, l0, l1, l2, l3;
    split_bf16(u4[0], h0, l0); split_bf16(u4[1], h1, l1);
    split_bf16(u4[2], h2, l2); split_bf16(u4[3], h3, l3);
    ((uint2*)g_u_hi)[i] = make_uint2(pack2(h0, h1), pack2(h2, h3));
    ((uint2*)g_u_lo)[i] = make_uint2(pack2(l0, l1), pack2(l2, l3));
}

// ---------------------------------------------------------------------------
// Reduce x_proj K-split partials -> g_xp fp32 + hi/lo
// ---------------------------------------------------------------------------
__global__ void xp_reduce_kernel() {
    int i = blockIdx.x * blockDim.x + threadIdx.x;
    if (i >= NTOK * XPC) return;
    float s = 0.0f;
#pragma unroll
    for (int z = 0; z < XP_KSPLIT; z++)
        s += g_xp_part[(size_t)z * NTOK * XPC + i];
    g_xp[i] = s;
    __nv_bfloat16 h, lo;
    split_bf16(s, h, lo);
    g_xp_hi[i] = h;
    g_xp_lo[i] = lo;
}

// ---------------------------------------------------------------------------
// Chunked selective scan (R12 structure): 8 lanes per d-channel, 2 states/lane.
// Warp covers 4 d. Block: 256 threads = 8 warps = 32 d.
// Grid: (DINNER/32, L/CHUNK, B) = (64, 4, 2).
// u reconstructed from bf16 hi/lo (prefetched one t ahead); writes y fp32.
// ---------------------------------------------------------------------------
__global__ __launch_bounds__(256)
void scan_kernel(const float* __restrict__ A_log) {
    __shared__ float sBC[CHUNK][2 * NSTATE];
    const int b = blockIdx.z;
    const int c = blockIdx.y;
    const int tid = threadIdx.x;
    const int lane = tid & 31, wid = tid >> 5;
    const int g = lane >> 3;            // d within warp (0..3)
    const int j = lane & 7;             // state pair index (handles j and j+8)
    const int d = blockIdx.x * 32 + wid * 4 + g;
    const size_t row0 = (size_t)(b * LSEQ + c * CHUNK);

    for (int i = tid; i < CHUNK * 32; i += 256) {
        int t = i >> 5, k = i & 31;
        sBC[t][k] = g_xp[(row0 + t) * XPC + DTRANK + k];
    }

    const float A0 = -__expf(__ldg(A_log + d * NSTATE + j));
    const float A1 = -__expf(__ldg(A_log + d * NSTATE + j + 8));
    float s0 = 0.0f, s1 = 0.0f;
    __syncthreads();

    const float* dp = g_delta + row0 * DINNER + d;
    const __nv_bfloat16* uhp = g_u_hi + row0 * DINNER + d;
    const __nv_bfloat16* ulp = g_u_lo + row0 * DINNER + d;
    float* yp = g_y + row0 * DINNER + d;

    float dl = dp[0];
    float ut = __bfloat162float(uhp[0]) + __bfloat162float(ulp[0]);
#pragma unroll 2
    for (int t = 0; t < CHUNK; t++) {
        float dln = 0.f, utn = 0.f;
        if (t + 1 < CHUNK) {
            dln = __ldg(dp + (size_t)(t + 1) * DINNER);
            utn = __bfloat162float(__ldg(uhp + (size_t)(t + 1) * DINNER)) +
                  __bfloat162float(__ldg(ulp + (size_t)(t + 1) * DINNER));
        }
        float du = dl * ut;
        float a0 = __expf(dl * A0);
        float a1 = __expf(dl * A1);
        s0 = fmaf(a0, s0, du * sBC[t][j]);
        s1 = fmaf(a1, s1, du * sBC[t][j + 8]);
        float p = fmaf(s1, sBC[t][NSTATE + j + 8], s0 * sBC[t][j + NSTATE]);
        p += __shfl_xor_sync(0xffffffffu, p, 1, 8);
        p += __shfl_xor_sync(0xffffffffu, p, 2, 8);
        p += __shfl_xor_sync(0xffffffffu, p, 4, 8);
        if (j == 0) yp[(size_t)t * DINNER] = p;
        dl = dln; ut = utn;
    }
}

// ---------------------------------------------------------------------------
// Gate: g = y * silu(res) -> hi/lo bf16 (A operand of out_proj), x4
// ---------------------------------------------------------------------------
__global__ void gate_kernel() {
    int i = blockIdx.x * blockDim.x + threadIdx.x;   // over NTOK*DINNER/4
    if (i >= NTOK * DINNER / 4) return;
    int d4 = (i & (DINNER / 4 - 1)) * 4;
    int bl = i / (DINNER / 4);
    float4 res = *(const float4*)(g_xr + (size_t)bl * (2 * DINNER) + DINNER + d4);
    float4 y = *(const float4*)(g_y + (size_t)bl * DINNER + d4);
    float v0 = y.x * silu_f(res.x);
    float v1 = y.y * silu_f(res.y);
    float v2 = y.z * silu_f(res.z);
    float v3 = y.w * silu_f(res.w);
    __nv_bfloat16 h0, h1, h2, h3, l0, l1, l2, l3;
    split_bf16(v0, h0, l0); split_bf16(v1, h1, l1);
    split_bf16(v2, h2, l2); split_bf16(v3, h3, l3);
    ((uint2*)g_g_hi)[i] = make_uint2(pack2(h0, h1), pack2(h2, h3));
    ((uint2*)g_g_lo)[i] = make_uint2(pack2(l0, l1), pack2(l2, l3));
}

// ---------------------------------------------------------------------------
// Host launch
// ---------------------------------------------------------------------------
extern "C" void kernel_launch(void* const* d_in, const int* in_sizes, int n_in,
                              void* d_out, int out_size) {
    const float* x      = (const float*)d_in[0];
    const float* W_in   = (const float*)d_in[1];
    const float* b_in   = (const float*)d_in[2];
    const float* conv_w = (const float*)d_in[3];
    const float* conv_b = (const float*)d_in[4];
    const float* W_x    = (const float*)d_in[5];
    const float* W_dt   = (const float*)d_in[6];
    const float* b_dt   = (const float*)d_in[7];
    const float* A_log  = (const float*)d_in[8];
    const float* W_out  = (const float*)d_in[9];
    const float* b_out  = (const float*)d_in[10];
    float* out = (float*)d_out;

    cudaFuncSetAttribute(gemm_mma_kernel<0>, cudaFuncAttributeMaxDynamicSharedMemorySize, GEMM_SMEM);
    cudaFuncSetAttribute(gemm_mma_kernel<1>, cudaFuncAttributeMaxDynamicSharedMemorySize, GEMM_SMEM);

    float *p_xr, *p_xp_part, *p_delta;
    cudaGetSymbolAddress((void**)&p_xr, g_xr);
    cudaGetSymbolAddress((void**)&p_xp_part, g_xp_part);
    cudaGetSymbolAddress((void**)&p_delta, g_delta);

    __nv_bfloat16 *xh, *xl, *wih, *wil, *wxh, *wxl, *wdh, *wdl, *woh, *wol;
    __nv_bfloat16 *uh, *ul, *xph, *xpl, *gh, *gl;
    cudaGetSymbolAddress((void**)&xh, g_x_hi);    cudaGetSymbolAddress((void**)&xl, g_x_lo);
    cudaGetSymbolAddress((void**)&wih, g_Win_hi); cudaGetSymbolAddress((void**)&wil, g_Win_lo);
    cudaGetSymbolAddress((void**)&wxh, g_Wx_hi);  cudaGetSymbolAddress((void**)&wxl, g_Wx_lo);
    cudaGetSymbolAddress((void**)&wdh, g_Wdt_hi); cudaGetSymbolAddress((void**)&wdl, g_Wdt_lo);
    cudaGetSymbolAddress((void**)&woh, g_Wout_hi); cudaGetSymbolAddress((void**)&wol, g_Wout_lo);
    cudaGetSymbolAddress((void**)&uh, g_u_hi);    cudaGetSymbolAddress((void**)&ul, g_u_lo);
    cudaGetSymbolAddress((void**)&xph, g_xp_hi);  cudaGetSymbolAddress((void**)&xpl, g_xp_lo);
    cudaGetSymbolAddress((void**)&gh, g_g_hi);    cudaGetSymbolAddress((void**)&gl, g_g_lo);

    // 0) all split-bf16 conversions in one launch
    cvt_all_kernel<<<(CV4 + 255) / 256, 256>>>(x, W_in, W_x, W_dt, W_out);

    // 1) in_proj: xr = x @ W_in^T + b_in   (2048 x 4096, K=1024)
    gemm_mma_kernel<0><<<dim3(32, 16, 1), 512, GEMM_SMEM>>>(
        xh, xl, DMODEL, wih, wil, DMODEL, b_in, p_xr, 2 * DINNER, 2 * DINNER, 1024, 0);

    // 2) depthwise conv + SiLU -> u (bf16 hi/lo only)
    conv_silu_kernel<<<(NTOK * DINNER / 4 + 255) / 256, 256>>>(conv_w, conv_b);

    // 3) x_proj: xp = u @ W_x^T  (2048 x 96, K=2048), K-split 8 + reduce
    gemm_mma_kernel<0><<<dim3(1, 16, XP_KSPLIT), 512, GEMM_SMEM>>>(
        uh, ul, DINNER, wxh, wxl, DINNER, nullptr, p_xp_part, XPC, XPC,
        DINNER / XP_KSPLIT, (long)NTOK * XPC);
    xp_reduce_kernel<<<(NTOK * XPC + 255) / 256, 256>>>();

    // 4) delta = softplus(dlt @ W_dt^T + b_dt)  (2048 x 2048, K=64)
    gemm_mma_kernel<1><<<dim3(16, 16, 1), 512, GEMM_SMEM>>>(
        xph, xpl, XPC, wdh, wdl, DTRANK, b_dt, p_delta, DINNER, DINNER, 64, 0);

    // 5) chunked selective scan (8 lanes per d, 2 states per lane) -> y
    scan_kernel<<<dim3(DINNER / 32, LSEQ / CHUNK, BSZ), 256>>>(A_log);

    // 6) gate: g = y * silu(res)
    gate_kernel<<<(NTOK * DINNER / 4 + 255) / 256, 256>>>();

    // 7) out = g @ W_out^T + b_out  (2048 x 1024, K=2048)
    gemm_mma_kernel<0><<<dim3(8, 16, 1), 512, GEMM_SMEM>>>(
        gh, gl, DINNER, woh, wol, DINNER, b_out, out, DMODEL, DMODEL, 2048, 0);
}

// round 16
// speedup vs baseline: 1.1943x; 1.0256x over previous
#include <cuda_runtime.h>
#include <cuda_bf16.h>
#include <math.h>
#include <stdint.h>

// Problem constants
#define BSZ 2
#define LSEQ 1024
#define DMODEL 1024
#define DINNER 2048
#define NSTATE 16
#define DTRANK 64
#define CHUNK 256
#define NTOK (BSZ*LSEQ)          // 2048
#define XPC (DTRANK + 2*NSTATE)  // 96
#define XP_KSPLIT 8

// ---------------------------------------------------------------------------
// Low-level helpers
// ---------------------------------------------------------------------------
__device__ __forceinline__ uint32_t smem_to_u32(const void* p) {
    uint32_t a;
    asm("{ .reg .u64 t; cvta.to.shared.u64 t, %1; cvt.u32.u64 %0, t; }" : "=r"(a) : "l"(p));
    return a;
}
__device__ __forceinline__ void cp16(uint32_t dst, const void* src) {
    asm volatile("cp.async.cg.shared.global [%0], [%1], 16;" :: "r"(dst), "l"(src));
}
__device__ __forceinline__ void ldsm_x4(uint32_t* r, uint32_t addr) {
    asm volatile("ldmatrix.sync.aligned.m8n8.x4.shared.b16 {%0,%1,%2,%3}, [%4];"
                 : "=r"(r[0]), "=r"(r[1]), "=r"(r[2]), "=r"(r[3]) : "r"(addr));
}
__device__ __forceinline__ void mma16816(float* c, const uint32_t* a, const uint32_t* b) {
    asm volatile(
        "mma.sync.aligned.m16n8k16.row.col.f32.bf16.bf16.f32 "
        "{%0,%1,%2,%3}, {%4,%5,%6,%7}, {%8,%9}, {%0,%1,%2,%3};"
        : "+f"(c[0]), "+f"(c[1]), "+f"(c[2]), "+f"(c[3])
        : "r"(a[0]), "r"(a[1]), "r"(a[2]), "r"(a[3]), "r"(b[0]), "r"(b[1]));
}

// ---------------------------------------------------------------------------
// Scratch (device globals)
// ---------------------------------------------------------------------------
__device__ __align__(16) float g_xr[(size_t)NTOK * 2 * DINNER];
__device__ __align__(16) float g_xp[(size_t)NTOK * XPC];
__device__ __align__(16) float g_xp_part[(size_t)XP_KSPLIT * NTOK * XPC];
__device__ __align__(16) float g_delta[(size_t)NTOK * DINNER];
__device__ __align__(16) float g_y[(size_t)NTOK * DINNER];

__device__ __align__(16) __nv_bfloat16 g_x_hi[(size_t)NTOK * DMODEL];
__device__ __align__(16) __nv_bfloat16 g_x_lo[(size_t)NTOK * DMODEL];
__device__ __align__(16) __nv_bfloat16 g_Win_hi[(size_t)2 * DINNER * DMODEL];
__device__ __align__(16) __nv_bfloat16 g_Win_lo[(size_t)2 * DINNER * DMODEL];
__device__ __align__(16) __nv_bfloat16 g_Wx_hi[(size_t)XPC * DINNER];
__device__ __align__(16) __nv_bfloat16 g_Wx_lo[(size_t)XPC * DINNER];
__device__ __align__(16) __nv_bfloat16 g_Wdt_hi[(size_t)DINNER * DTRANK];
__device__ __align__(16) __nv_bfloat16 g_Wdt_lo[(size_t)DINNER * DTRANK];
__device__ __align__(16) __nv_bfloat16 g_Wout_hi[(size_t)DMODEL * DINNER];
__device__ __align__(16) __nv_bfloat16 g_Wout_lo[(size_t)DMODEL * DINNER];
__device__ __align__(16) __nv_bfloat16 g_u_hi[(size_t)NTOK * DINNER];
__device__ __align__(16) __nv_bfloat16 g_u_lo[(size_t)NTOK * DINNER];
__device__ __align__(16) __nv_bfloat16 g_xp_hi[(size_t)NTOK * XPC];
__device__ __align__(16) __nv_bfloat16 g_xp_lo[(size_t)NTOK * XPC];
__device__ __align__(16) __nv_bfloat16 g_g_hi[(size_t)NTOK * DINNER];
__device__ __align__(16) __nv_bfloat16 g_g_lo[(size_t)NTOK * DINNER];

__device__ __forceinline__ float silu_f(float x) { return x / (1.0f + __expf(-x)); }
__device__ __forceinline__ void split_bf16(float v, __nv_bfloat16& h, __nv_bfloat16& l) {
    h = __float2bfloat16(v);
    l = __float2bfloat16(v - __bfloat162float(h));
}
__device__ __forceinline__ uint32_t pack2(__nv_bfloat16 a, __nv_bfloat16 b) {
    return ((uint32_t)__bfloat16_as_ushort(b) << 16) | (uint32_t)__bfloat16_as_ushort(a);
}

// ---------------------------------------------------------------------------
// One merged conversion kernel for all fp32 -> (hi,lo) bf16 splits
// ---------------------------------------------------------------------------
#define CV0 (NTOK * DMODEL / 4)
#define CV1 (CV0 + 2 * DINNER * DMODEL / 4)
#define CV2 (CV1 + XPC * DINNER / 4)
#define CV3 (CV2 + DINNER * DTRANK / 4)
#define CV4 (CV3 + DMODEL * DINNER / 4)

__device__ __forceinline__ void cvt4(const float* __restrict__ in,
                                     __nv_bfloat16* __restrict__ hi,
                                     __nv_bfloat16* __restrict__ lo, int i) {
    float4 v = ((const float4*)in)[i];
    __nv_bfloat16 h0, h1, h2, h3, l0, l1, l2, l3;
    split_bf16(v.x, h0, l0); split_bf16(v.y, h1, l1);
    split_bf16(v.z, h2, l2); split_bf16(v.w, h3, l3);
    ((uint2*)hi)[i] = make_uint2(pack2(h0, h1), pack2(h2, h3));
    ((uint2*)lo)[i] = make_uint2(pack2(l0, l1), pack2(l2, l3));
}

__global__ void cvt_all_kernel(const float* __restrict__ x,
                               const float* __restrict__ Wi,
                               const float* __restrict__ Wx,
                               const float* __restrict__ Wd,
                               const float* __restrict__ Wo) {
    int i = blockIdx.x * blockDim.x + threadIdx.x;
    if (i < CV0)            cvt4(x,  g_x_hi,   g_x_lo,   i);
    else if (i < CV1)       cvt4(Wi, g_Win_hi, g_Win_lo, i - CV0);
    else if (i < CV2)       cvt4(Wx, g_Wx_hi,  g_Wx_lo,  i - CV1);
    else if (i < CV3)       cvt4(Wd, g_Wdt_hi, g_Wdt_lo, i - CV2);
    else if (i < CV4)       cvt4(Wo, g_Wout_hi, g_Wout_lo, i - CV3);
}

// ---------------------------------------------------------------------------
// mma.sync split-bf16 GEMM: CTA 128x128, BK=32, 512 threads, warp tile 32x32.
// 3-stage cp.async pipeline with ONE __syncthreads per iteration.
// 3-term accumulation: AhiWhi + AhiWlo + AloWhi (fp32 accum in registers).
// ---------------------------------------------------------------------------
#define STG_BYTES 32768      // per stage: 4 tiles x 8192
#define NSTAGE 3
#define GEMM_SMEM (NSTAGE * STG_BYTES)   // 98304

__device__ __forceinline__ uint32_t swz(int row, int c) {
    return (uint32_t)(row * 64 + ((c ^ ((row >> 1) & 3)) << 4));
}

template<int ACT>
__global__ __launch_bounds__(512, 1)
void gemm_mma_kernel(const __nv_bfloat16* __restrict__ Ahi, const __nv_bfloat16* __restrict__ Alo, int lda,
                     const __nv_bfloat16* __restrict__ Whi, const __nv_bfloat16* __restrict__ Wlo, int ldw,
                     const float* __restrict__ bias, float* __restrict__ C, int ldc,
                     int Nvalid, int K, long czstride) {
    extern __shared__ __align__(1024) char smem[];
    const uint32_t sbase = smem_to_u32(smem);
    const int tid = threadIdx.x;
    const int lane = tid & 31, wid = tid >> 5;
    const int wm = wid & 3, wn = wid >> 2;
    const int bm = blockIdx.y * 128, bn = blockIdx.x * 128;
    const int kbase = blockIdx.z * K;
    float* Cz = C + (size_t)blockIdx.z * czstride;

    // zero-fill W tile rows >= Nvalid (xp case), all 3 stages, both W tiles
    if (bn + 128 > Nvalid) {
        for (int j = tid; j < NSTAGE * 2 * 128 * 4; j += 512) {
            int c = j & 3, r = (j >> 2) & 127, t = (j >> 9) & 1, s = j >> 10;
            if (bn + r >= Nvalid)
                *(uint4*)(smem + s * STG_BYTES + (2 + t) * 8192 + swz(r, c)) = make_uint4(0, 0, 0, 0);
        }
        __syncthreads();
    }

    const int nIter = K / 32;
    const int r = tid >> 2, c = tid & 3;
    const uint32_t dswz = swz(r, c);
    const bool wok = (bn + r < Nvalid);

    auto issue = [&](int stage, int k0) {
        uint32_t dst = sbase + stage * STG_BYTES + dswz;
        const char* a0 = (const char*)Ahi + ((size_t)(bm + r) * lda + k0) * 2 + c * 16;
        const char* a1 = (const char*)Alo + ((size_t)(bm + r) * lda + k0) * 2 + c * 16;
        cp16(dst, a0);
        cp16(dst + 8192, a1);
        if (wok) {
            const char* w0 = (const char*)Whi + ((size_t)(bn + r) * ldw + k0) * 2 + c * 16;
            const char* w1 = (const char*)Wlo + ((size_t)(bn + r) * ldw + k0) * 2 + c * 16;
            cp16(dst + 16384, w0);
            cp16(dst + 24576, w1);
        }
    };

    // prologue: stages 0 and 1 in flight (second commit may be empty if nIter==1)
    issue(0, kbase);
    asm volatile("cp.async.commit_group;" ::: "memory");
    if (nIter > 1) issue(1, kbase + 32);
    asm volatile("cp.async.commit_group;" ::: "memory");

    float acc[2][4][4];
#pragma unroll
    for (int mi = 0; mi < 2; mi++)
#pragma unroll
        for (int nt = 0; nt < 4; nt++)
#pragma unroll
            for (int q = 0; q < 4; q++) acc[mi][nt][q] = 0.0f;

    for (int it = 0; it < nIter; it++) {
        if (it + 1 < nIter) asm volatile("cp.async.wait_group 1;" ::: "memory");
        else                asm volatile("cp.async.wait_group 0;" ::: "memory");
        __syncthreads();

        // prefetch into the stage consumed 2 iterations ago (all threads past sync)
        if (it + 2 < nIter) issue((it + 2) % NSTAGE, kbase + (it + 2) * 32);
        asm volatile("cp.async.commit_group;" ::: "memory");   // one group per iter (empty ok)

        const int buf = it % NSTAGE;
        const uint32_t sA_hi = sbase + buf * STG_BYTES;
        const uint32_t sA_lo = sA_hi + 8192;
        const uint32_t sW_hi = sA_hi + 16384;
        const uint32_t sW_lo = sA_hi + 24576;

#pragma unroll
        for (int ks = 0; ks < 2; ks++) {
            uint32_t ah[2][4], al[2][4], bh[4][2], bl[4][2];
#pragma unroll
            for (int mi = 0; mi < 2; mi++) {
                int rr = wm * 32 + mi * 16 + (lane & 15);
                int kc = 2 * ks + (lane >> 4);
                uint32_t addr = swz(rr, kc);
                ldsm_x4(ah[mi], sA_hi + addr);
                ldsm_x4(al[mi], sA_lo + addr);
            }
#pragma unroll
            for (int njp = 0; njp < 2; njp++) {
                int seg = lane >> 3;
                int rr = wn * 32 + njp * 16 + ((seg >> 1) << 3) + (lane & 7);
                int kc = 2 * ks + (seg & 1);
                uint32_t addr = swz(rr, kc);
                uint32_t t0[4], t1[4];
                ldsm_x4(t0, sW_hi + addr);
                ldsm_x4(t1, sW_lo + addr);
                bh[njp * 2][0] = t0[0]; bh[njp * 2][1] = t0[1];
                bh[njp * 2 + 1][0] = t0[2]; bh[njp * 2 + 1][1] = t0[3];
                bl[njp * 2][0] = t1[0]; bl[njp * 2][1] = t1[1];
                bl[njp * 2 + 1][0] = t1[2]; bl[njp * 2 + 1][1] = t1[3];
            }
#pragma unroll
            for (int mi = 0; mi < 2; mi++)
#pragma unroll
                for (int nt = 0; nt < 4; nt++) {
                    mma16816(acc[mi][nt], ah[mi], bh[nt]);
                    mma16816(acc[mi][nt], ah[mi], bl[nt]);
                    mma16816(acc[mi][nt], al[mi], bh[nt]);
                }
        }
    }

    // epilogue: direct register stores
    const int g = lane >> 2, tig = lane & 3;
#pragma unroll
    for (int mi = 0; mi < 2; mi++) {
        int m0 = bm + wm * 32 + mi * 16 + g;
#pragma unroll
        for (int nt = 0; nt < 4; nt++) {
            int n = bn + wn * 32 + nt * 8 + tig * 2;
            if (n < Nvalid) {
                float b0 = bias ? bias[n] : 0.0f;
                float b1 = bias ? bias[n + 1] : 0.0f;
                float v0 = acc[mi][nt][0] + b0, v1 = acc[mi][nt][1] + b1;
                float v2 = acc[mi][nt][2] + b0, v3 = acc[mi][nt][3] + b1;
                if (ACT == 1) {
                    v0 = (v0 > 20.0f) ? v0 : log1pf(__expf(v0));
                    v1 = (v1 > 20.0f) ? v1 : log1pf(__expf(v1));
                    v2 = (v2 > 20.0f) ? v2 : log1pf(__expf(v2));
                    v3 = (v3 > 20.0f) ? v3 : log1pf(__expf(v3));
                }
                *(float2*)&Cz[(size_t)m0 * ldc + n] = make_float2(v0, v1);
                *(float2*)&Cz[(size_t)(m0 + 8) * ldc + n] = make_float2(v2, v3);
            }
        }
    }
}

// ---------------------------------------------------------------------------
// Depthwise causal conv1d (k=3) + bias + SiLU -> u hi/lo bf16 only, x4
// ---------------------------------------------------------------------------
__global__ void conv_silu_kernel(const float* __restrict__ cw,
                                 const float* __restrict__ cb) {
    int i = blockIdx.x * blockDim.x + threadIdx.x;   // over NTOK*DINNER/4
    if (i >= NTOK * DINNER / 4) return;
    int d4 = (i & (DINNER / 4 - 1)) * 4;
    int bl = i / (DINNER / 4);
    int l = bl & (LSEQ - 1);

    const float* base = g_xr + (size_t)bl * (2 * DINNER) + d4;
    float4 cur = *(const float4*)base;
    float4 p1 = make_float4(0, 0, 0, 0), p2 = p1;
    if (l >= 1) p1 = *(const float4*)(base - 2 * DINNER);
    if (l >= 2) p2 = *(const float4*)(base - 4 * DINNER);

    float u4[4];
#pragma unroll
    for (int q = 0; q < 4; q++) {
        int d = d4 + q;
        float w0 = __ldg(cw + d * 3 + 0);
        float w1 = __ldg(cw + d * 3 + 1);
        float w2 = __ldg(cw + d * 3 + 2);
        float c = (&cur.x)[q], a = (&p1.x)[q], b = (&p2.x)[q];
        float acc = __ldg(cb + d) + w2 * c;
        acc = fmaf(w1, a, acc);
        acc = fmaf(w0, b, acc);
        u4[q] = silu_f(acc);
    }
    __nv_bfloat16 h0, h1, h2, h3, l0, l1, l2, l3;
    split_bf16(u4[0], h0, l0); split_bf16(u4[1], h1, l1);
    split_bf16(u4[2], h2, l2); split_bf16(u4[3], h3, l3);
    ((uint2*)g_u_hi)[i] = make_uint2(pack2(h0, h1), pack2(h2, h3));
    ((uint2*)g_u_lo)[i] = make_uint2(pack2(l0, l1), pack2(l2, l3));
}

// ---------------------------------------------------------------------------
// Reduce x_proj K-split partials -> g_xp fp32 + hi/lo
// ---------------------------------------------------------------------------
__global__ void xp_reduce_kernel() {
    int i = blockIdx.x * blockDim.x + threadIdx.x;
    if (i >= NTOK * XPC) return;
    float s = 0.0f;
#pragma unroll
    for (int z = 0; z < XP_KSPLIT; z++)
        s += g_xp_part[(size_t)z * NTOK * XPC + i];
    g_xp[i] = s;
    __nv_bfloat16 h, lo;
    split_bf16(s, h, lo);
    g_xp_hi[i] = h;
    g_xp_lo[i] = lo;
}

// ---------------------------------------------------------------------------
// Chunked selective scan: 8 lanes per d-channel, 2 states/lane.
// Warp covers 4 d. Block: 256 threads = 8 warps = 32 d.
// Grid: (DINNER/32, L/CHUNK, B) = (64, 4, 2).
// u reconstructed from bf16 hi/lo (prefetched one t ahead); writes y fp32.
// ---------------------------------------------------------------------------
__global__ __launch_bounds__(256)
void scan_kernel(const float* __restrict__ A_log) {
    __shared__ float sBC[CHUNK][2 * NSTATE];
    const int b = blockIdx.z;
    const int c = blockIdx.y;
    const int tid = threadIdx.x;
    const int lane = tid & 31, wid = tid >> 5;
    const int g = lane >> 3;            // d within warp (0..3)
    const int j = lane & 7;             // state pair index (handles j and j+8)
    const int d = blockIdx.x * 32 + wid * 4 + g;
    const size_t row0 = (size_t)(b * LSEQ + c * CHUNK);

    for (int i = tid; i < CHUNK * 32; i += 256) {
        int t = i >> 5, k = i & 31;
        sBC[t][k] = g_xp[(row0 + t) * XPC + DTRANK + k];
    }

    const float A0 = -__expf(__ldg(A_log + d * NSTATE + j));
    const float A1 = -__expf(__ldg(A_log + d * NSTATE + j + 8));
    float s0 = 0.0f, s1 = 0.0f;
    __syncthreads();

    const float* dp = g_delta + row0 * DINNER + d;
    const __nv_bfloat16* uhp = g_u_hi + row0 * DINNER + d;
    const __nv_bfloat16* ulp = g_u_lo + row0 * DINNER + d;
    float* yp = g_y + row0 * DINNER + d;

    float dl = dp[0];
    float ut = __bfloat162float(uhp[0]) + __bfloat162float(ulp[0]);
#pragma unroll 2
    for (int t = 0; t < CHUNK; t++) {
        float dln = 0.f, utn = 0.f;
        if (t + 1 < CHUNK) {
            dln = __ldg(dp + (size_t)(t + 1) * DINNER);
            utn = __bfloat162float(__ldg(uhp + (size_t)(t + 1) * DINNER)) +
                  __bfloat162float(__ldg(ulp + (size_t)(t + 1) * DINNER));
        }
        float du = dl * ut;
        float a0 = __expf(dl * A0);
        float a1 = __expf(dl * A1);
        s0 = fmaf(a0, s0, du * sBC[t][j]);
        s1 = fmaf(a1, s1, du * sBC[t][j + 8]);
        float p = fmaf(s1, sBC[t][NSTATE + j + 8], s0 * sBC[t][j + NSTATE]);
        p += __shfl_xor_sync(0xffffffffu, p, 1, 8);
        p += __shfl_xor_sync(0xffffffffu, p, 2, 8);
        p += __shfl_xor_sync(0xffffffffu, p, 4, 8);
        if (j == 0) yp[(size_t)t * DINNER] = p;
        dl = dln; ut = utn;
    }
}

// ---------------------------------------------------------------------------
// Gate: g = y * silu(res) -> hi/lo bf16 (A operand of out_proj), x4
// ---------------------------------------------------------------------------
__global__ void gate_kernel() {
    int i = blockIdx.x * blockDim.x + threadIdx.x;   // over NTOK*DINNER/4
    if (i >= NTOK * DINNER / 4) return;
    int d4 = (i & (DINNER / 4 - 1)) * 4;
    int bl = i / (DINNER / 4);
    float4 res = *(const float4*)(g_xr + (size_t)bl * (2 * DINNER) + DINNER + d4);
    float4 y = *(const float4*)(g_y + (size_t)bl * DINNER + d4);
    float v0 = y.x * silu_f(res.x);
    float v1 = y.y * silu_f(res.y);
    float v2 = y.z * silu_f(res.z);
    float v3 = y.w * silu_f(res.w);
    __nv_bfloat16 h0, h1, h2, h3, l0, l1, l2, l3;
    split_bf16(v0, h0, l0); split_bf16(v1, h1, l1);
    split_bf16(v2, h2, l2); split_bf16(v3, h3, l3);
    ((uint2*)g_g_hi)[i] = make_uint2(pack2(h0, h1), pack2(h2, h3));
    ((uint2*)g_g_lo)[i] = make_uint2(pack2(l0, l1), pack2(l2, l3));
}

// ---------------------------------------------------------------------------
// Host launch
// ---------------------------------------------------------------------------
extern "C" void kernel_launch(void* const* d_in, const int* in_sizes, int n_in,
                              void* d_out, int out_size) {
    const float* x      = (const float*)d_in[0];
    const float* W_in   = (const float*)d_in[1];
    const float* b_in   = (const float*)d_in[2];
    const float* conv_w = (const float*)d_in[3];
    const float* conv_b = (const float*)d_in[4];
    const float* W_x    = (const float*)d_in[5];
    const float* W_dt   = (const float*)d_in[6];
    const float* b_dt   = (const float*)d_in[7];
    const float* A_log  = (const float*)d_in[8];
    const float* W_out  = (const float*)d_in[9];
    const float* b_out  = (const float*)d_in[10];
    float* out = (float*)d_out;

    cudaFuncSetAttribute(gemm_mma_kernel<0>, cudaFuncAttributeMaxDynamicSharedMemorySize, GEMM_SMEM);
    cudaFuncSetAttribute(gemm_mma_kernel<1>, cudaFuncAttributeMaxDynamicSharedMemorySize, GEMM_SMEM);

    float *p_xr, *p_xp_part, *p_delta;
    cudaGetSymbolAddress((void**)&p_xr, g_xr);
    cudaGetSymbolAddress((void**)&p_xp_part, g_xp_part);
    cudaGetSymbolAddress((void**)&p_delta, g_delta);

    __nv_bfloat16 *xh, *xl, *wih, *wil, *wxh, *wxl, *wdh, *wdl, *woh, *wol;
    __nv_bfloat16 *uh, *ul, *xph, *xpl, *gh, *gl;
    cudaGetSymbolAddress((void**)&xh, g_x_hi);    cudaGetSymbolAddress((void**)&xl, g_x_lo);
    cudaGetSymbolAddress((void**)&wih, g_Win_hi); cudaGetSymbolAddress((void**)&wil, g_Win_lo);
    cudaGetSymbolAddress((void**)&wxh, g_Wx_hi);  cudaGetSymbolAddress((void**)&wxl, g_Wx_lo);
    cudaGetSymbolAddress((void**)&wdh, g_Wdt_hi); cudaGetSymbolAddress((void**)&wdl, g_Wdt_lo);
    cudaGetSymbolAddress((void**)&woh, g_Wout_hi); cudaGetSymbolAddress((void**)&wol, g_Wout_lo);
    cudaGetSymbolAddress((void**)&uh, g_u_hi);    cudaGetSymbolAddress((void**)&ul, g_u_lo);
    cudaGetSymbolAddress((void**)&xph, g_xp_hi);  cudaGetSymbolAddress((void**)&xpl, g_xp_lo);
    cudaGetSymbolAddress((void**)&gh, g_g_hi);    cudaGetSymbolAddress((void**)&gl, g_g_lo);

    // 0) all split-bf16 conversions in one launch
    cvt_all_kernel<<<(CV4 + 255) / 256, 256>>>(x, W_in, W_x, W_dt, W_out);

    // 1) in_proj: xr = x @ W_in^T + b_in   (2048 x 4096, K=1024)
    gemm_mma_kernel<0><<<dim3(32, 16, 1), 512, GEMM_SMEM>>>(
        xh, xl, DMODEL, wih, wil, DMODEL, b_in, p_xr, 2 * DINNER, 2 * DINNER, 1024, 0);

    // 2) depthwise conv + SiLU -> u (bf16 hi/lo only)
    conv_silu_kernel<<<(NTOK * DINNER / 4 + 255) / 256, 256>>>(conv_w, conv_b);

    // 3) x_proj: xp = u @ W_x^T  (2048 x 96, K=2048), K-split 8 + reduce
    gemm_mma_kernel<0><<<dim3(1, 16, XP_KSPLIT), 512, GEMM_SMEM>>>(
        uh, ul, DINNER, wxh, wxl, DINNER, nullptr, p_xp_part, XPC, XPC,
        DINNER / XP_KSPLIT, (long)NTOK * XPC);
    xp_reduce_kernel<<<(NTOK * XPC + 255) / 256, 256>>>();

    // 4) delta = softplus(dlt @ W_dt^T + b_dt)  (2048 x 2048, K=64)
    gemm_mma_kernel<1><<<dim3(16, 16, 1), 512, GEMM_SMEM>>>(
        xph, xpl, XPC, wdh, wdl, DTRANK, b_dt, p_delta, DINNER, DINNER, 64, 0);

    // 5) chunked selective scan (8 lanes per d, 2 states per lane) -> y
    scan_kernel<<<dim3(DINNER / 32, LSEQ / CHUNK, BSZ), 256>>>(A_log);

    // 6) gate: g = y * silu(res)
    gate_kernel<<<(NTOK * DINNER / 4 + 255) / 256, 256>>>();

    // 7) out = g @ W_out^T + b_out  (2048 x 1024, K=2048)
    gemm_mma_kernel<0><<<dim3(8, 16, 1), 512, GEMM_SMEM>>>(
        gh, gl, DINNER, woh, wol, DINNER, b_out, out, DMODEL, DMODEL, 2048, 0);
}